// round 1
// baseline (speedup 1.0000x reference)
#include <cuda_runtime.h>
#include <math.h>

#define SEQ   4096
#define EMB   1024
#define NH    16
#define HD    64
#define NE3   3072   // 3*EMB

// Scratch (allocation-free rule: __device__ globals)
__device__ float g_qkv[SEQ * NE3];   // [S, 3E]  (q | k | v per row)
__device__ float g_att[SEQ * EMB];   // [S, E]   attention output (head-merged)

// ---------------------------------------------------------------------------
// SGEMM: C[M,N] = A[M,K] @ B[K,N] + bias[N]
// BM=BN=128, BK=8, 256 threads, 8x8 per-thread microtile.
// Requires M%128==0, N%128==0, K%8==0 (true for all our shapes).
// ---------------------------------------------------------------------------
__global__ __launch_bounds__(256) void sgemm_bias_kernel(
    const float* __restrict__ A, const float* __restrict__ B,
    const float* __restrict__ bias, float* __restrict__ C,
    int M, int N, int K)
{
    __shared__ float As[8][128];   // transposed A tile
    __shared__ float Bs[8][128];

    const int tid = threadIdx.x;
    const int tx = tid & 15;       // 0..15
    const int ty = tid >> 4;       // 0..15
    const int m0 = blockIdx.y * 128;
    const int n0 = blockIdx.x * 128;

    // load indices
    const int a_row = tid >> 1;          // 0..127
    const int a_col = (tid & 1) * 4;     // 0 or 4
    const int b_row = tid >> 5;          // 0..7
    const int b_col = (tid & 31) * 4;    // 0..124

    float acc[8][8];
    #pragma unroll
    for (int i = 0; i < 8; i++)
        #pragma unroll
        for (int j = 0; j < 8; j++) acc[i][j] = 0.f;

    for (int k0 = 0; k0 < K; k0 += 8) {
        float4 av = *(const float4*)(A + (size_t)(m0 + a_row) * K + (k0 + a_col));
        As[a_col + 0][a_row] = av.x;
        As[a_col + 1][a_row] = av.y;
        As[a_col + 2][a_row] = av.z;
        As[a_col + 3][a_row] = av.w;
        float4 bv = *(const float4*)(B + (size_t)(k0 + b_row) * N + (n0 + b_col));
        *(float4*)&Bs[b_row][b_col] = bv;
        __syncthreads();

        #pragma unroll
        for (int kk = 0; kk < 8; kk++) {
            float af[8], bf[8];
            #pragma unroll
            for (int i = 0; i < 8; i++) af[i] = As[kk][ty * 8 + i];
            #pragma unroll
            for (int j = 0; j < 8; j++) bf[j] = Bs[kk][tx * 8 + j];
            #pragma unroll
            for (int i = 0; i < 8; i++)
                #pragma unroll
                for (int j = 0; j < 8; j++)
                    acc[i][j] = fmaf(af[i], bf[j], acc[i][j]);
        }
        __syncthreads();
    }

    // epilogue with bias
    #pragma unroll
    for (int i = 0; i < 8; i++) {
        const int r = m0 + ty * 8 + i;
        #pragma unroll
        for (int j4 = 0; j4 < 2; j4++) {
            const int c = n0 + tx * 8 + j4 * 4;
            float4 ov;
            ov.x = acc[i][j4 * 4 + 0] + bias[c + 0];
            ov.y = acc[i][j4 * 4 + 1] + bias[c + 1];
            ov.z = acc[i][j4 * 4 + 2] + bias[c + 2];
            ov.w = acc[i][j4 * 4 + 3] + bias[c + 3];
            *(float4*)(C + (size_t)r * N + c) = ov;
        }
    }
}

// ---------------------------------------------------------------------------
// Flash attention (causal, NO 1/sqrt(D) scale), fp32.
// Grid: (32 q-tiles, 16 heads); 128 threads; thread i owns q-row qt*128+i.
// K/V read straight out of g_qkv (strided rows, contiguous 64-float segments).
// Score chunks of 32 to bound registers; smem K/V reads are warp-uniform
// addresses -> broadcast (no bank conflicts, 4 FMAs per LDS.128).
// ---------------------------------------------------------------------------
__global__ __launch_bounds__(128) void flash_attn_kernel(
    const float* __restrict__ qkv, float* __restrict__ att)
{
    const int h  = blockIdx.y;
    const int qt = gridDim.x - 1 - blockIdx.x;   // heavy diagonal blocks first
    const int tid = threadIdx.x;
    const int qi  = qt * 128 + tid;

    __shared__ float Ks[64][64];
    __shared__ float Vs[64][64];

    // load q row into registers
    float q[HD];
    {
        const float4* qrow = (const float4*)(qkv + (size_t)qi * NE3 + h * HD);
        #pragma unroll
        for (int i = 0; i < 16; i++) {
            float4 v = qrow[i];
            q[4*i+0] = v.x; q[4*i+1] = v.y; q[4*i+2] = v.z; q[4*i+3] = v.w;
        }
    }

    float o[HD];
    #pragma unroll
    for (int d = 0; d < HD; d++) o[d] = 0.f;
    float m = -INFINITY, l = 0.f;

    const size_t koff = (size_t)EMB     + h * HD;  // K block offset within a qkv row
    const size_t voff = (size_t)2 * EMB + h * HD;

    const int nkt = 2 * qt + 2;   // k-tiles (64 rows each) covering rows <= qt*128+127
    for (int kt = 0; kt < nkt; kt++) {
        // cooperative load of K/V tiles: 64x64 floats each, 8 float4 per thread
        #pragma unroll
        for (int i = 0; i < 8; i++) {
            const int f   = tid + i * 128;     // 0..1023
            const int row = f >> 4;            // 0..63
            const int c4  = (f & 15) * 4;      // 0..60
            const size_t srow = (size_t)(kt * 64 + row) * NE3;
            *(float4*)&Ks[row][c4] = *(const float4*)(qkv + srow + koff + c4);
            *(float4*)&Vs[row][c4] = *(const float4*)(qkv + srow + voff + c4);
        }
        __syncthreads();

        const int k0 = kt * 64;
        if (k0 <= qi) {
            #pragma unroll
            for (int jc = 0; jc < 2; jc++) {      // two 32-wide score chunks
                float s[32];
                float mt = -INFINITY;
                #pragma unroll
                for (int j = 0; j < 32; j++) {
                    const int jj = jc * 32 + j;
                    float a = 0.f;
                    #pragma unroll
                    for (int d4 = 0; d4 < 16; d4++) {
                        float4 kv = *(const float4*)&Ks[jj][d4 * 4];
                        a = fmaf(q[4*d4+0], kv.x, a);
                        a = fmaf(q[4*d4+1], kv.y, a);
                        a = fmaf(q[4*d4+2], kv.z, a);
                        a = fmaf(q[4*d4+3], kv.w, a);
                    }
                    s[j] = (k0 + jj <= qi) ? a : -INFINITY;
                    mt = fmaxf(mt, s[j]);
                }
                if (mt != -INFINITY) {
                    const float mnew = fmaxf(m, mt);
                    const float corr = __expf(m - mnew);   // m==-inf -> 0
                    m = mnew;
                    l *= corr;
                    #pragma unroll
                    for (int d = 0; d < HD; d++) o[d] *= corr;
                    #pragma unroll
                    for (int j = 0; j < 32; j++) {
                        const float p = __expf(s[j] - mnew);   // -inf -> 0
                        l += p;
                        const int jj = jc * 32 + j;
                        #pragma unroll
                        for (int d4 = 0; d4 < 16; d4++) {
                            float4 vv = *(const float4*)&Vs[jj][d4 * 4];
                            o[4*d4+0] = fmaf(p, vv.x, o[4*d4+0]);
                            o[4*d4+1] = fmaf(p, vv.y, o[4*d4+1]);
                            o[4*d4+2] = fmaf(p, vv.z, o[4*d4+2]);
                            o[4*d4+3] = fmaf(p, vv.w, o[4*d4+3]);
                        }
                    }
                }
            }
        }
        __syncthreads();
    }

    // normalize and store: att[qi, h*64 + d]
    const float inv = 1.f / l;
    float4* orow = (float4*)(att + (size_t)qi * EMB + h * HD);
    #pragma unroll
    for (int i = 0; i < 16; i++) {
        float4 v;
        v.x = o[4*i+0] * inv; v.y = o[4*i+1] * inv;
        v.z = o[4*i+2] * inv; v.w = o[4*i+3] * inv;
        orow[i] = v;
    }
}

// ---------------------------------------------------------------------------
// kernel_launch
// inputs: 0:x [1,4096,1024] f32, 1:masked_matrix (ignored, causal),
//         2:Wqkv [1024,3072], 3:bqkv [3072], 4:Wp [1024,1024], 5:bp [1024]
// out: [1,4096,1024] f32
// ---------------------------------------------------------------------------
extern "C" void kernel_launch(void* const* d_in, const int* in_sizes, int n_in,
                              void* d_out, int out_size)
{
    const float* x    = (const float*)d_in[0];
    const float* Wqkv = (const float*)d_in[2];
    const float* bqkv = (const float*)d_in[3];
    const float* Wp   = (const float*)d_in[4];
    const float* bp   = (const float*)d_in[5];
    float* out = (float*)d_out;

    float* qkv; cudaGetSymbolAddress((void**)&qkv, g_qkv);
    float* att; cudaGetSymbolAddress((void**)&att, g_att);

    // 1) QKV projection: [4096,1024] @ [1024,3072] + bqkv -> g_qkv
    {
        dim3 grid(NE3 / 128, SEQ / 128);
        sgemm_bias_kernel<<<grid, 256>>>(x, Wqkv, bqkv, qkv, SEQ, NE3, EMB);
    }
    // 2) causal flash attention -> g_att [S, E]
    {
        dim3 grid(SEQ / 128, NH);
        flash_attn_kernel<<<grid, 128>>>(qkv, att);
    }
    // 3) output projection: [4096,1024] @ [1024,1024] + bp -> out
    {
        dim3 grid(EMB / 128, SEQ / 128);
        sgemm_bias_kernel<<<grid, 256>>>(att, Wp, bp, out, SEQ, EMB, EMB);
    }
}

// round 2
// speedup vs baseline: 1.7330x; 1.7330x over previous
#include <cuda_runtime.h>
#include <math.h>
#include <stdint.h>

#define SEQ   4096
#define EMB   1024
#define NH    16
#define HD    64
#define NE3   3072   // 3*EMB

// Scratch (allocation-free rule: __device__ globals)
__device__ float g_qkv[SEQ * NE3];   // [S, 3E]  (q | k | v per row)
__device__ float g_att[SEQ * EMB];   // [S, E]   attention output (head-merged)

// ---------------------------------------------------------------------------
// SGEMM: C[M,N] = A[M,K] @ B[K,N] + bias[N]   (unchanged from R1, passing)
// ---------------------------------------------------------------------------
__global__ __launch_bounds__(256) void sgemm_bias_kernel(
    const float* __restrict__ A, const float* __restrict__ B,
    const float* __restrict__ bias, float* __restrict__ C,
    int M, int N, int K)
{
    __shared__ float As[8][128];
    __shared__ float Bs[8][128];

    const int tid = threadIdx.x;
    const int tx = tid & 15;
    const int ty = tid >> 4;
    const int m0 = blockIdx.y * 128;
    const int n0 = blockIdx.x * 128;

    const int a_row = tid >> 1;
    const int a_col = (tid & 1) * 4;
    const int b_row = tid >> 5;
    const int b_col = (tid & 31) * 4;

    float acc[8][8];
    #pragma unroll
    for (int i = 0; i < 8; i++)
        #pragma unroll
        for (int j = 0; j < 8; j++) acc[i][j] = 0.f;

    for (int k0 = 0; k0 < K; k0 += 8) {
        float4 av = *(const float4*)(A + (size_t)(m0 + a_row) * K + (k0 + a_col));
        As[a_col + 0][a_row] = av.x;
        As[a_col + 1][a_row] = av.y;
        As[a_col + 2][a_row] = av.z;
        As[a_col + 3][a_row] = av.w;
        float4 bv = *(const float4*)(B + (size_t)(k0 + b_row) * N + (n0 + b_col));
        *(float4*)&Bs[b_row][b_col] = bv;
        __syncthreads();

        #pragma unroll
        for (int kk = 0; kk < 8; kk++) {
            float af[8], bf[8];
            #pragma unroll
            for (int i = 0; i < 8; i++) af[i] = As[kk][ty * 8 + i];
            #pragma unroll
            for (int j = 0; j < 8; j++) bf[j] = Bs[kk][tx * 8 + j];
            #pragma unroll
            for (int i = 0; i < 8; i++)
                #pragma unroll
                for (int j = 0; j < 8; j++)
                    acc[i][j] = fmaf(af[i], bf[j], acc[i][j]);
        }
        __syncthreads();
    }

    #pragma unroll
    for (int i = 0; i < 8; i++) {
        const int r = m0 + ty * 8 + i;
        #pragma unroll
        for (int j4 = 0; j4 < 2; j4++) {
            const int c = n0 + tx * 8 + j4 * 4;
            float4 ov;
            ov.x = acc[i][j4 * 4 + 0] + bias[c + 0];
            ov.y = acc[i][j4 * 4 + 1] + bias[c + 1];
            ov.z = acc[i][j4 * 4 + 2] + bias[c + 2];
            ov.w = acc[i][j4 * 4 + 3] + bias[c + 3];
            *(float4*)(C + (size_t)r * N + c) = ov;
        }
    }
}

// ---------------------------------------------------------------------------
// tf32 helpers
// ---------------------------------------------------------------------------
__device__ __forceinline__ unsigned tf32_of(float x) {
    unsigned u;
    asm("cvt.rna.tf32.f32 %0, %1;" : "=r"(u) : "f"(x));
    return u;
}
// split x into (hi, lo) tf32 pair, x ~= hi + lo to ~2^-22 relative
__device__ __forceinline__ float2 split2(float x) {
    float hi = __uint_as_float(tf32_of(x));
    float lo = __uint_as_float(tf32_of(x - hi));
    return make_float2(hi, lo);
}

__device__ __forceinline__ void mma8(float4& d,
    unsigned a0, unsigned a1, unsigned a2, unsigned a3,
    unsigned b0, unsigned b1)
{
    asm volatile(
        "mma.sync.aligned.m16n8k8.row.col.f32.tf32.tf32.f32 "
        "{%0,%1,%2,%3},{%4,%5,%6,%7},{%8,%9},{%0,%1,%2,%3};\n"
        : "+f"(d.x), "+f"(d.y), "+f"(d.z), "+f"(d.w)
        : "r"(a0), "r"(a1), "r"(a2), "r"(a3), "r"(b0), "r"(b1));
}

// 3xTF32: d += a*b with a,b given as (hi,lo) float2 fragments
__device__ __forceinline__ void mma3x(float4& d,
    float2 a0, float2 a1, float2 a2, float2 a3,
    float2 b0, float2 b1)
{
    unsigned a0h = __float_as_uint(a0.x), a1h = __float_as_uint(a1.x);
    unsigned a2h = __float_as_uint(a2.x), a3h = __float_as_uint(a3.x);
    unsigned a0l = __float_as_uint(a0.y), a1l = __float_as_uint(a1.y);
    unsigned a2l = __float_as_uint(a2.y), a3l = __float_as_uint(a3.y);
    unsigned b0h = __float_as_uint(b0.x), b1h = __float_as_uint(b1.x);
    unsigned b0l = __float_as_uint(b0.y), b1l = __float_as_uint(b1.y);
    mma8(d, a0h, a1h, a2h, a3h, b0l, b1l);   // hi * lo
    mma8(d, a0l, a1l, a2l, a3l, b0h, b1h);   // lo * hi
    mma8(d, a0h, a1h, a2h, a3h, b0h, b1h);   // hi * hi
}

// ---------------------------------------------------------------------------
// Flash attention, causal, NO 1/sqrt(D) scale. tf32 tensor cores (3xTF32).
// Grid: (32 q-tiles, 16 heads); 256 threads (8 warps); q-tile 128, k-tile 32.
// Warp w owns q-rows [16w, 16w+16). Online softmax per row in smem.
// ---------------------------------------------------------------------------
#define QPAD 66   // float2 row stride for Q/K/V tiles (64 + 2)
#define SPAD 33   // row stride for S (float) and P (float2)

#define QS(r,c) Qs[(r)*QPAD + (c)]
#define KS(r,c) Ks[(r)*QPAD + (c)]
#define VS(r,c) Vs[(r)*QPAD + (c)]
#define SS(r,c) Ss[(r)*SPAD + (c)]
#define PS(r,c) Ps[(r)*SPAD + (c)]

// bytes: Qs 128*66*8 + Ks 32*66*8 + Vs 32*66*8 + Ss 128*33*4 + Ps 128*33*8 + 4*128*4
#define FLASH_SMEM (128*QPAD*8 + 32*QPAD*8 + 32*QPAD*8 + 128*SPAD*4 + 128*SPAD*8 + 4*128*4)

__global__ __launch_bounds__(256) void flash_attn_tc_kernel(
    const float* __restrict__ qkv, float* __restrict__ att)
{
    extern __shared__ char smraw[];
    float2* Qs = (float2*)smraw;                 // [128][QPAD]
    float2* Ks = Qs + 128 * QPAD;                // [32][QPAD]
    float2* Vs = Ks + 32 * QPAD;                 // [32][QPAD]
    float*  Ss = (float*)(Vs + 32 * QPAD);       // [128][SPAD]
    float2* Ps = (float2*)(Ss + 128 * SPAD);     // [128][SPAD]
    float*  mrow = (float*)(Ps + 128 * SPAD);
    float*  lrow = mrow + 128;
    float*  crow = lrow + 128;
    float*  linv = crow + 128;

    const int h  = blockIdx.y;
    const int qt = gridDim.x - 1 - blockIdx.x;   // heavy diagonal blocks first
    const int tid  = threadIdx.x;
    const int w    = tid >> 5;
    const int lane = tid & 31;
    const int g    = lane >> 2;     // 0..7
    const int tg   = lane & 3;      // 0..3
    const int m0   = w * 16;        // warp's q-row band
    const int qbase = qt * 128;

    const size_t qoff = (size_t)h * HD;
    const size_t koff = (size_t)EMB + h * HD;
    const size_t voff = (size_t)2 * EMB + h * HD;

    // ---- load Q tile (128 x 64) as tf32 hi/lo pairs ----
    #pragma unroll
    for (int i = 0; i < 8; i++) {
        const int idx = tid + i * 256;       // 0..2047
        const int row = idx >> 4;            // 0..127
        const int c4  = (idx & 15) * 4;      // 0..60
        float4 v = *(const float4*)(qkv + (size_t)(qbase + row) * NE3 + qoff + c4);
        QS(row, c4 + 0) = split2(v.x);
        QS(row, c4 + 1) = split2(v.y);
        QS(row, c4 + 2) = split2(v.z);
        QS(row, c4 + 3) = split2(v.w);
    }
    if (tid < 128) { mrow[tid] = -INFINITY; lrow[tid] = 0.f; }

    // persistent O fragments: 8 n-frags covering d = 0..63, rows m0+g / m0+g+8
    float4 of[8];
    #pragma unroll
    for (int nf = 0; nf < 8; nf++) of[nf] = make_float4(0.f, 0.f, 0.f, 0.f);

    const int nkt = 4 * (qt + 1);   // 32-key tiles covering keys <= qbase+127
    for (int kt = 0; kt < nkt; kt++) {
        __syncthreads();  // Ks/Vs free (prev PV done), Ss free (prev softmax done)

        // ---- load K/V tile (32 x 64 each) as hi/lo pairs ----
        #pragma unroll
        for (int i = 0; i < 2; i++) {
            const int idx = tid + i * 256;   // 0..511
            const int row = idx >> 4;        // 0..31
            const int c4  = (idx & 15) * 4;
            const size_t srow = (size_t)(kt * 32 + row) * NE3;
            float4 kv = *(const float4*)(qkv + srow + koff + c4);
            KS(row, c4 + 0) = split2(kv.x);
            KS(row, c4 + 1) = split2(kv.y);
            KS(row, c4 + 2) = split2(kv.z);
            KS(row, c4 + 3) = split2(kv.w);
            float4 vv = *(const float4*)(qkv + srow + voff + c4);
            VS(row, c4 + 0) = split2(vv.x);
            VS(row, c4 + 1) = split2(vv.y);
            VS(row, c4 + 2) = split2(vv.z);
            VS(row, c4 + 3) = split2(vv.w);
        }
        __syncthreads();

        // ---- QK^T: S[128 x 32] = Q[128 x 64] * K^T ----
        float4 cf[4];
        #pragma unroll
        for (int nf = 0; nf < 4; nf++) cf[nf] = make_float4(0.f, 0.f, 0.f, 0.f);

        #pragma unroll
        for (int ks = 0; ks < 8; ks++) {
            const int k0 = ks * 8;
            float2 a0 = QS(m0 + g,     k0 + tg);
            float2 a1 = QS(m0 + g + 8, k0 + tg);
            float2 a2 = QS(m0 + g,     k0 + tg + 4);
            float2 a3 = QS(m0 + g + 8, k0 + tg + 4);
            #pragma unroll
            for (int nf = 0; nf < 4; nf++) {
                const int n0 = nf * 8;
                float2 b0 = KS(n0 + g, k0 + tg);
                float2 b1 = KS(n0 + g, k0 + tg + 4);
                mma3x(cf[nf], a0, a1, a2, a3, b0, b1);
            }
        }

        // ---- write S with causal mask ----
        {
            const int qr0 = qbase + m0 + g;
            const int qr1 = qr0 + 8;
            const int kb  = kt * 32;
            #pragma unroll
            for (int nf = 0; nf < 4; nf++) {
                const int c = nf * 8 + 2 * tg;
                SS(m0 + g,     c    ) = (kb + c     <= qr0) ? cf[nf].x : -INFINITY;
                SS(m0 + g,     c + 1) = (kb + c + 1 <= qr0) ? cf[nf].y : -INFINITY;
                SS(m0 + g + 8, c    ) = (kb + c     <= qr1) ? cf[nf].z : -INFINITY;
                SS(m0 + g + 8, c + 1) = (kb + c + 1 <= qr1) ? cf[nf].w : -INFINITY;
            }
        }
        __syncthreads();

        // ---- online softmax per row (threads 0..127) ----
        if (tid < 128) {
            const int r = tid;
            float mt = -INFINITY;
            #pragma unroll
            for (int c = 0; c < 32; c++) mt = fmaxf(mt, SS(r, c));
            const float mold = mrow[r];
            const float mnew = fmaxf(mold, mt);
            const float corr = __expf(mold - mnew);   // first tile: -inf -> 0
            float sum = 0.f;
            #pragma unroll
            for (int c = 0; c < 32; c++) {
                const float p = __expf(SS(r, c) - mnew);
                sum += p;
                PS(r, c) = split2(p);
            }
            lrow[r] = lrow[r] * corr + sum;
            mrow[r] = mnew;
            crow[r] = corr;
        }
        __syncthreads();

        // ---- PV: O = O*corr + P[128 x 32] * V[32 x 64] ----
        {
            const float c0 = crow[m0 + g];
            const float c1 = crow[m0 + g + 8];
            #pragma unroll
            for (int nf = 0; nf < 8; nf++) {
                of[nf].x *= c0; of[nf].y *= c0;
                of[nf].z *= c1; of[nf].w *= c1;
            }
            #pragma unroll
            for (int ks = 0; ks < 4; ks++) {
                const int k0 = ks * 8;
                float2 a0 = PS(m0 + g,     k0 + tg);
                float2 a1 = PS(m0 + g + 8, k0 + tg);
                float2 a2 = PS(m0 + g,     k0 + tg + 4);
                float2 a3 = PS(m0 + g + 8, k0 + tg + 4);
                #pragma unroll
                for (int nf = 0; nf < 8; nf++) {
                    const int n0 = nf * 8;
                    float2 b0 = VS(k0 + tg,     n0 + g);
                    float2 b1 = VS(k0 + tg + 4, n0 + g);
                    mma3x(of[nf], a0, a1, a2, a3, b0, b1);
                }
            }
        }
    }

    // ---- finalize: O /= l, write out ----
    __syncthreads();
    if (tid < 128) linv[tid] = 1.f / lrow[tid];
    __syncthreads();

    {
        const float i0 = linv[m0 + g];
        const float i1 = linv[m0 + g + 8];
        const int r0 = qbase + m0 + g;
        const int r1 = r0 + 8;
        #pragma unroll
        for (int nf = 0; nf < 8; nf++) {
            const int c = nf * 8 + 2 * tg;
            float2 v0 = make_float2(of[nf].x * i0, of[nf].y * i0);
            float2 v1 = make_float2(of[nf].z * i1, of[nf].w * i1);
            *(float2*)(att + (size_t)r0 * EMB + h * HD + c) = v0;
            *(float2*)(att + (size_t)r1 * EMB + h * HD + c) = v1;
        }
    }
}

// ---------------------------------------------------------------------------
// kernel_launch
// inputs: 0:x [1,4096,1024] f32, 1:masked_matrix (ignored, causal),
//         2:Wqkv [1024,3072], 3:bqkv [3072], 4:Wp [1024,1024], 5:bp [1024]
// out: [1,4096,1024] f32
// ---------------------------------------------------------------------------
extern "C" void kernel_launch(void* const* d_in, const int* in_sizes, int n_in,
                              void* d_out, int out_size)
{
    const float* x    = (const float*)d_in[0];
    const float* Wqkv = (const float*)d_in[2];
    const float* bqkv = (const float*)d_in[3];
    const float* Wp   = (const float*)d_in[4];
    const float* bp   = (const float*)d_in[5];
    float* out = (float*)d_out;

    float* qkv; cudaGetSymbolAddress((void**)&qkv, g_qkv);
    float* att; cudaGetSymbolAddress((void**)&att, g_att);

    // 1) QKV projection: [4096,1024] @ [1024,3072] + bqkv -> g_qkv
    {
        dim3 grid(NE3 / 128, SEQ / 128);
        sgemm_bias_kernel<<<grid, 256>>>(x, Wqkv, bqkv, qkv, SEQ, NE3, EMB);
    }
    // 2) causal flash attention (tf32 tensor cores) -> g_att [S, E]
    {
        cudaFuncSetAttribute(flash_attn_tc_kernel,
                             cudaFuncAttributeMaxDynamicSharedMemorySize,
                             FLASH_SMEM);
        dim3 grid(SEQ / 128, NH);
        flash_attn_tc_kernel<<<grid, 256, FLASH_SMEM>>>(qkv, att);
    }
    // 3) output projection: [4096,1024] @ [1024,1024] + bp -> out
    {
        dim3 grid(EMB / 128, SEQ / 128);
        sgemm_bias_kernel<<<grid, 256>>>(att, Wp, bp, out, SEQ, EMB, EMB);
    }
}

// round 3
// speedup vs baseline: 3.7586x; 2.1688x over previous
#include <cuda_runtime.h>
#include <cuda_bf16.h>
#include <math.h>
#include <stdint.h>

#define SEQ   4096
#define EMB   1024
#define NH    16
#define HD    64
#define NE3   3072   // 3*EMB

// Scratch (allocation-free rule: __device__ globals)
__device__ __nv_bfloat16 g_qkv_h[SEQ * NE3];  // split-hi of qkv
__device__ __nv_bfloat16 g_qkv_l[SEQ * NE3];  // split-lo of qkv
__device__ float g_att[SEQ * EMB];            // attention output (f32)

// ---------------------------------------------------------------------------
// helpers
// ---------------------------------------------------------------------------
__device__ __forceinline__ void mma_bf16(float4& d,
    uint32_t a0, uint32_t a1, uint32_t a2, uint32_t a3,
    uint32_t b0, uint32_t b1)
{
    asm volatile(
        "mma.sync.aligned.m16n8k16.row.col.f32.bf16.bf16.f32 "
        "{%0,%1,%2,%3},{%4,%5,%6,%7},{%8,%9},{%0,%1,%2,%3};\n"
        : "+f"(d.x), "+f"(d.y), "+f"(d.z), "+f"(d.w)
        : "r"(a0), "r"(a1), "r"(a2), "r"(a3), "r"(b0), "r"(b1));
}

// split (x,y) into packed bf16x2 hi and lo words; x in low half (even col)
__device__ __forceinline__ void split2b(float x, float y, uint32_t& hi, uint32_t& lo) {
    uint32_t h;
    asm("cvt.rn.bf16x2.f32 %0, %1, %2;" : "=r"(h) : "f"(y), "f"(x));
    float hx = __uint_as_float(h << 16);
    float hy = __uint_as_float(h & 0xffff0000u);
    uint32_t l;
    asm("cvt.rn.bf16x2.f32 %0, %1, %2;" : "=r"(l) : "f"(y - hy), "f"(x - hx));
    hi = h; lo = l;
}

// ---------------------------------------------------------------------------
// bf16x3 GEMM: C[M,N] = A[M,K] @ B[K,N] + bias
// 128x128 block tile, BK=32, 256 threads (8 warps, 2x4), warp tile 64x32.
// A pre-split into packed bf16x2 hi/lo smem (stride 20 words, conflict-free);
// B raw f32 in smem, split at fragment-load time.
// SPLIT_OUT: write bf16 hi/lo arrays instead of f32.
// ---------------------------------------------------------------------------
#define GBK 32

template<bool SPLIT_OUT>
__global__ __launch_bounds__(256) void gemm_bf16x3_kernel(
    const float* __restrict__ A, const float* __restrict__ B,
    const float* __restrict__ bias, float* __restrict__ Cf,
    __nv_bfloat16* __restrict__ Chi, __nv_bfloat16* __restrict__ Clo,
    int M, int N, int K)
{
    __shared__ uint32_t Ash[128 * 20];
    __shared__ uint32_t Asl[128 * 20];
    __shared__ float    Bsf[32 * 132];

    const int tid  = threadIdx.x;
    const int w    = tid >> 5;
    const int lane = tid & 31;
    const int g    = lane >> 2;
    const int tg   = lane & 3;
    const int wm   = (w >> 2) * 64;   // warp tile m origin (0 or 64)
    const int wn   = (w & 3) * 32;    // warp tile n origin
    const int m_blk = blockIdx.y * 128;
    const int n_blk = blockIdx.x * 128;

    float4 acc[4][4];
    #pragma unroll
    for (int i = 0; i < 4; i++)
        #pragma unroll
        for (int j = 0; j < 4; j++) acc[i][j] = make_float4(0.f, 0.f, 0.f, 0.f);

    for (int k0 = 0; k0 < K; k0 += GBK) {
        // ---- A tile: 128 x 32 f32, split to packed hi/lo ----
        #pragma unroll
        for (int i = 0; i < 4; i++) {
            const int f   = tid + i * 256;     // 0..1023
            const int row = f >> 3;
            const int c4  = (f & 7) * 4;
            float4 v = *(const float4*)(A + (size_t)(m_blk + row) * K + k0 + c4);
            uint32_t h0, l0, h1, l1;
            split2b(v.x, v.y, h0, l0);
            split2b(v.z, v.w, h1, l1);
            Ash[row * 20 + c4 / 2]     = h0;
            Ash[row * 20 + c4 / 2 + 1] = h1;
            Asl[row * 20 + c4 / 2]     = l0;
            Asl[row * 20 + c4 / 2 + 1] = l1;
        }
        // ---- B tile: 32 x 128 f32 raw ----
        #pragma unroll
        for (int i = 0; i < 4; i++) {
            const int f   = tid + i * 256;     // 0..1023
            const int row = f >> 5;
            const int n4  = (f & 31) * 4;
            *(float4*)&Bsf[row * 132 + n4] =
                *(const float4*)(B + (size_t)(k0 + row) * N + n_blk + n4);
        }
        __syncthreads();

        #pragma unroll
        for (int ks = 0; ks < 2; ks++) {
            uint32_t ah[4][4], al[4][4];
            #pragma unroll
            for (int mf = 0; mf < 4; mf++) {
                const int r0 = wm + mf * 16 + g;
                const int r1 = r0 + 8;
                const int cp = ks * 8 + tg;
                ah[mf][0] = Ash[r0 * 20 + cp];     al[mf][0] = Asl[r0 * 20 + cp];
                ah[mf][1] = Ash[r1 * 20 + cp];     al[mf][1] = Asl[r1 * 20 + cp];
                ah[mf][2] = Ash[r0 * 20 + cp + 4]; al[mf][2] = Asl[r0 * 20 + cp + 4];
                ah[mf][3] = Ash[r1 * 20 + cp + 4]; al[mf][3] = Asl[r1 * 20 + cp + 4];
            }
            #pragma unroll
            for (int nf = 0; nf < 4; nf++) {
                const int n  = wn + nf * 8 + g;
                const int kr = ks * 16 + 2 * tg;
                uint32_t b0h, b0l, b1h, b1l;
                split2b(Bsf[kr * 132 + n],       Bsf[(kr + 1) * 132 + n], b0h, b0l);
                split2b(Bsf[(kr + 8) * 132 + n], Bsf[(kr + 9) * 132 + n], b1h, b1l);
                #pragma unroll
                for (int mf = 0; mf < 4; mf++) {
                    mma_bf16(acc[mf][nf], ah[mf][0], ah[mf][1], ah[mf][2], ah[mf][3], b0l, b1l);
                    mma_bf16(acc[mf][nf], al[mf][0], al[mf][1], al[mf][2], al[mf][3], b0h, b1h);
                    mma_bf16(acc[mf][nf], ah[mf][0], ah[mf][1], ah[mf][2], ah[mf][3], b0h, b1h);
                }
            }
        }
        __syncthreads();
    }

    // ---- epilogue: bias add, store ----
    #pragma unroll
    for (int nf = 0; nf < 4; nf++) {
        const int c  = n_blk + wn + nf * 8 + 2 * tg;
        const float bc0 = bias[c];
        const float bc1 = bias[c + 1];
        #pragma unroll
        for (int mf = 0; mf < 4; mf++) {
            const int r0 = m_blk + wm + mf * 16 + g;
            const int r1 = r0 + 8;
            float v00 = acc[mf][nf].x + bc0;
            float v01 = acc[mf][nf].y + bc1;
            float v10 = acc[mf][nf].z + bc0;
            float v11 = acc[mf][nf].w + bc1;
            if (SPLIT_OUT) {
                uint32_t h, l;
                split2b(v00, v01, h, l);
                ((uint32_t*)Chi)[((size_t)r0 * N + c) >> 1] = h;
                ((uint32_t*)Clo)[((size_t)r0 * N + c) >> 1] = l;
                split2b(v10, v11, h, l);
                ((uint32_t*)Chi)[((size_t)r1 * N + c) >> 1] = h;
                ((uint32_t*)Clo)[((size_t)r1 * N + c) >> 1] = l;
            } else {
                *(float2*)(Cf + (size_t)r0 * N + c) = make_float2(v00, v01);
                *(float2*)(Cf + (size_t)r1 * N + c) = make_float2(v10, v11);
            }
        }
    }
}

// ---------------------------------------------------------------------------
// Flash attention, causal, NO 1/sqrt(D) scale. bf16x3 m16n8k16 tensor cores.
// Grid (32 q-tiles, 16 heads), 256 threads (8 warps), q-tile 128, k-tile 64.
// Q fragments in registers; register softmax with shfl reductions;
// P smem is warp-private (syncwarp only).
// ---------------------------------------------------------------------------
#define KPAD 36   // word stride (36*4g+tg conflict-free; uint4-aligned)
#define ATT_SMEM ((64*KPAD*2 + 64*KPAD*2 + 128*KPAD*2) * 4)

__global__ __launch_bounds__(256) void flash_attn_bf16_kernel(
    const __nv_bfloat16* __restrict__ qhi,
    const __nv_bfloat16* __restrict__ qlo,
    float* __restrict__ att)
{
    extern __shared__ uint32_t sm[];
    uint32_t* Ksh = sm;                     // K hi  [key][36] packed pairs
    uint32_t* Ksl = Ksh + 64 * KPAD;        // K lo
    uint32_t* Vsh = Ksl + 64 * KPAD;        // V^T hi: bf16 view [feat][72]
    uint32_t* Vsl = Vsh + 64 * KPAD;        // V^T lo
    uint32_t* Psh = Vsl + 64 * KPAD;        // P hi [row][36]   (also Q staging)
    uint32_t* Psl = Psh + 128 * KPAD;       // P lo

    const int h   = blockIdx.y;
    const int qt  = gridDim.x - 1 - blockIdx.x;  // heavy diagonal first
    const int tid = threadIdx.x;
    const int w    = tid >> 5;
    const int lane = tid & 31;
    const int g    = lane >> 2;
    const int tg   = lane & 3;
    const int m0   = w * 16;
    const int qbase = qt * 128;

    const uint4* qh4 = (const uint4*)qhi;   // row pitch: NE3/8 = 384 uint4
    const uint4* ql4 = (const uint4*)qlo;

    // ---- stage Q tile (128 x 64 bf16, hi+lo) into Psh/Psl ----
    #pragma unroll
    for (int i = 0; i < 4; i++) {
        const int f   = tid + i * 256;   // 0..1023
        const int row = f >> 3;
        const int c   = f & 7;           // uint4 within row
        const size_t gidx = (size_t)(qbase + row) * 384 + h * 8 + c;
        *(uint4*)&Psh[row * KPAD + c * 4] = qh4[gidx];
        *(uint4*)&Psl[row * KPAD + c * 4] = ql4[gidx];
    }
    __syncthreads();

    // ---- Q fragments to registers ----
    uint32_t qah[4][4], qal[4][4];
    #pragma unroll
    for (int ks = 0; ks < 4; ks++) {
        const int cp = ks * 8 + tg;
        qah[ks][0] = Psh[(m0 + g) * KPAD + cp];
        qah[ks][1] = Psh[(m0 + g + 8) * KPAD + cp];
        qah[ks][2] = Psh[(m0 + g) * KPAD + cp + 4];
        qah[ks][3] = Psh[(m0 + g + 8) * KPAD + cp + 4];
        qal[ks][0] = Psl[(m0 + g) * KPAD + cp];
        qal[ks][1] = Psl[(m0 + g + 8) * KPAD + cp];
        qal[ks][2] = Psl[(m0 + g) * KPAD + cp + 4];
        qal[ks][3] = Psl[(m0 + g + 8) * KPAD + cp + 4];
    }

    float4 of[8];
    #pragma unroll
    for (int nf = 0; nf < 8; nf++) of[nf] = make_float4(0.f, 0.f, 0.f, 0.f);
    float mr0 = -INFINITY, mr1 = -INFINITY, lr0 = 0.f, lr1 = 0.f;

    const int nkt = 2 * (qt + 1);
    for (int kt = 0; kt < nkt; kt++) {
        __syncthreads();   // K/V (and staging on first iter) free to overwrite

        // ---- load K (natural) and V (transposed) tiles, 64 keys ----
        const int kb = kt * 64;
        #pragma unroll
        for (int i = 0; i < 2; i++) {
            const int f   = tid + i * 256;  // 0..511
            const int key = f >> 3;
            const int c   = f & 7;
            const size_t rb = (size_t)(kb + key) * 384 + h * 8 + c;
            // K at element offset EMB -> 128 uint4; V at 2*EMB -> 256 uint4
            *(uint4*)&Ksh[key * KPAD + c * 4] = qh4[rb + 128];
            *(uint4*)&Ksl[key * KPAD + c * 4] = ql4[rb + 128];
            uint4 vh = qh4[rb + 256];
            uint4 vl = ql4[rb + 256];
            unsigned short* vbh = (unsigned short*)Vsh;
            unsigned short* vbl = (unsigned short*)Vsl;
            const uint32_t wh[4] = {vh.x, vh.y, vh.z, vh.w};
            const uint32_t wl[4] = {vl.x, vl.y, vl.z, vl.w};
            #pragma unroll
            for (int j = 0; j < 4; j++) {
                const int fb = c * 8 + 2 * j;
                vbh[(size_t)fb * (KPAD * 2) + key]       = (unsigned short)(wh[j] & 0xffff);
                vbh[(size_t)(fb + 1) * (KPAD * 2) + key] = (unsigned short)(wh[j] >> 16);
                vbl[(size_t)fb * (KPAD * 2) + key]       = (unsigned short)(wl[j] & 0xffff);
                vbl[(size_t)(fb + 1) * (KPAD * 2) + key] = (unsigned short)(wl[j] >> 16);
            }
        }
        __syncthreads();

        // ---- QK^T: S[128 x 64] ----
        float4 cf[8];
        #pragma unroll
        for (int nf = 0; nf < 8; nf++) cf[nf] = make_float4(0.f, 0.f, 0.f, 0.f);
        #pragma unroll
        for (int ks = 0; ks < 4; ks++) {
            const int kk = ks * 8 + tg;
            #pragma unroll
            for (int nf = 0; nf < 8; nf++) {
                const int kr = (nf * 8 + g) * KPAD;
                uint32_t b0h = Ksh[kr + kk], b1h = Ksh[kr + kk + 4];
                uint32_t b0l = Ksl[kr + kk], b1l = Ksl[kr + kk + 4];
                mma_bf16(cf[nf], qah[ks][0], qah[ks][1], qah[ks][2], qah[ks][3], b0l, b1l);
                mma_bf16(cf[nf], qal[ks][0], qal[ks][1], qal[ks][2], qal[ks][3], b0h, b1h);
                mma_bf16(cf[nf], qah[ks][0], qah[ks][1], qah[ks][2], qah[ks][3], b0h, b1h);
            }
        }

        // ---- causal mask (only last two tiles can cross the diagonal) ----
        if (kt >= 2 * qt) {
            const int qr0 = qbase + m0 + g;
            const int qr1 = qr0 + 8;
            #pragma unroll
            for (int nf = 0; nf < 8; nf++) {
                const int c0 = kb + nf * 8 + 2 * tg;
                if (c0 > qr0)     cf[nf].x = -INFINITY;
                if (c0 + 1 > qr0) cf[nf].y = -INFINITY;
                if (c0 > qr1)     cf[nf].z = -INFINITY;
                if (c0 + 1 > qr1) cf[nf].w = -INFINITY;
            }
        }

        // ---- register softmax (rows m0+g and m0+g+8) ----
        float mt0 = -INFINITY, mt1 = -INFINITY;
        #pragma unroll
        for (int nf = 0; nf < 8; nf++) {
            mt0 = fmaxf(mt0, fmaxf(cf[nf].x, cf[nf].y));
            mt1 = fmaxf(mt1, fmaxf(cf[nf].z, cf[nf].w));
        }
        mt0 = fmaxf(mt0, __shfl_xor_sync(0xffffffffu, mt0, 1));
        mt0 = fmaxf(mt0, __shfl_xor_sync(0xffffffffu, mt0, 2));
        mt1 = fmaxf(mt1, __shfl_xor_sync(0xffffffffu, mt1, 1));
        mt1 = fmaxf(mt1, __shfl_xor_sync(0xffffffffu, mt1, 2));

        const float mn0 = fmaxf(mr0, mt0);
        const float mn1 = fmaxf(mr1, mt1);
        const float corr0 = __expf(mr0 - mn0);
        const float corr1 = __expf(mr1 - mn1);
        mr0 = mn0; mr1 = mn1;

        float s0 = 0.f, s1 = 0.f;
        #pragma unroll
        for (int nf = 0; nf < 8; nf++) {
            float p00 = __expf(cf[nf].x - mn0);
            float p01 = __expf(cf[nf].y - mn0);
            float p10 = __expf(cf[nf].z - mn1);
            float p11 = __expf(cf[nf].w - mn1);
            s0 += p00 + p01;
            s1 += p10 + p11;
            uint32_t hh, ll;
            split2b(p00, p01, hh, ll);
            Psh[(m0 + g) * KPAD + nf * 4 + tg] = hh;
            Psl[(m0 + g) * KPAD + nf * 4 + tg] = ll;
            split2b(p10, p11, hh, ll);
            Psh[(m0 + g + 8) * KPAD + nf * 4 + tg] = hh;
            Psl[(m0 + g + 8) * KPAD + nf * 4 + tg] = ll;
        }
        s0 += __shfl_xor_sync(0xffffffffu, s0, 1);
        s0 += __shfl_xor_sync(0xffffffffu, s0, 2);
        s1 += __shfl_xor_sync(0xffffffffu, s1, 1);
        s1 += __shfl_xor_sync(0xffffffffu, s1, 2);
        lr0 = lr0 * corr0 + s0;
        lr1 = lr1 * corr1 + s1;

        // ---- rescale O, then PV ----
        #pragma unroll
        for (int nf = 0; nf < 8; nf++) {
            of[nf].x *= corr0; of[nf].y *= corr0;
            of[nf].z *= corr1; of[nf].w *= corr1;
        }
        __syncwarp();   // P rows are warp-private

        #pragma unroll
        for (int ks = 0; ks < 4; ks++) {
            const int cp = ks * 8 + tg;
            uint32_t a0h = Psh[(m0 + g) * KPAD + cp];
            uint32_t a1h = Psh[(m0 + g + 8) * KPAD + cp];
            uint32_t a2h = Psh[(m0 + g) * KPAD + cp + 4];
            uint32_t a3h = Psh[(m0 + g + 8) * KPAD + cp + 4];
            uint32_t a0l = Psl[(m0 + g) * KPAD + cp];
            uint32_t a1l = Psl[(m0 + g + 8) * KPAD + cp];
            uint32_t a2l = Psl[(m0 + g) * KPAD + cp + 4];
            uint32_t a3l = Psl[(m0 + g + 8) * KPAD + cp + 4];
            #pragma unroll
            for (int nf = 0; nf < 8; nf++) {
                const int vr = (nf * 8 + g) * KPAD;
                uint32_t b0h = Vsh[vr + cp], b1h = Vsh[vr + cp + 4];
                uint32_t b0l = Vsl[vr + cp], b1l = Vsl[vr + cp + 4];
                mma_bf16(of[nf], a0h, a1h, a2h, a3h, b0l, b1l);
                mma_bf16(of[nf], a0l, a1l, a2l, a3l, b0h, b1h);
                mma_bf16(of[nf], a0h, a1h, a2h, a3h, b0h, b1h);
            }
        }
    }

    // ---- finalize ----
    const float i0 = 1.f / lr0;
    const float i1 = 1.f / lr1;
    const int r0 = qbase + m0 + g;
    const int r1 = r0 + 8;
    #pragma unroll
    for (int nf = 0; nf < 8; nf++) {
        const int c = h * HD + nf * 8 + 2 * tg;
        *(float2*)(att + (size_t)r0 * EMB + c) = make_float2(of[nf].x * i0, of[nf].y * i0);
        *(float2*)(att + (size_t)r1 * EMB + c) = make_float2(of[nf].z * i1, of[nf].w * i1);
    }
}

// ---------------------------------------------------------------------------
// kernel_launch
// ---------------------------------------------------------------------------
extern "C" void kernel_launch(void* const* d_in, const int* in_sizes, int n_in,
                              void* d_out, int out_size)
{
    const float* x    = (const float*)d_in[0];
    const float* Wqkv = (const float*)d_in[2];
    const float* bqkv = (const float*)d_in[3];
    const float* Wp   = (const float*)d_in[4];
    const float* bp   = (const float*)d_in[5];
    float* out = (float*)d_out;

    __nv_bfloat16* qkvh; cudaGetSymbolAddress((void**)&qkvh, g_qkv_h);
    __nv_bfloat16* qkvl; cudaGetSymbolAddress((void**)&qkvl, g_qkv_l);
    float* att; cudaGetSymbolAddress((void**)&att, g_att);

    // 1) QKV projection -> split bf16 hi/lo
    {
        dim3 grid(NE3 / 128, SEQ / 128);
        gemm_bf16x3_kernel<true><<<grid, 256>>>(
            x, Wqkv, bqkv, nullptr, qkvh, qkvl, SEQ, NE3, EMB);
    }
    // 2) causal flash attention (bf16x3 tensor cores) -> g_att f32
    {
        cudaFuncSetAttribute(flash_attn_bf16_kernel,
                             cudaFuncAttributeMaxDynamicSharedMemorySize,
                             ATT_SMEM);
        dim3 grid(SEQ / 128, NH);
        flash_attn_bf16_kernel<<<grid, 256, ATT_SMEM>>>(qkvh, qkvl, att);
    }
    // 3) output projection -> f32 out
    {
        dim3 grid(EMB / 128, SEQ / 128);
        gemm_bf16x3_kernel<false><<<grid, 256>>>(
            att, Wp, bp, out, nullptr, nullptr, SEQ, EMB, EMB);
    }
}

// round 4
// speedup vs baseline: 3.8989x; 1.0373x over previous
#include <cuda_runtime.h>
#include <cuda_bf16.h>
#include <math.h>
#include <stdint.h>

#define SEQ   4096
#define EMB   1024
#define NH    16
#define HD    64
#define NE3   3072   // 3*EMB

// Scratch (allocation-free rule: __device__ globals)
__device__ __nv_bfloat16 g_x_h[SEQ * EMB];     // split x
__device__ __nv_bfloat16 g_x_l[SEQ * EMB];
__device__ __nv_bfloat16 g_wqkv_h[NE3 * EMB];  // Wqkv^T split  [N][K]
__device__ __nv_bfloat16 g_wqkv_l[NE3 * EMB];
__device__ __nv_bfloat16 g_wp_h[EMB * EMB];    // Wp^T split    [N][K]
__device__ __nv_bfloat16 g_wp_l[EMB * EMB];
__device__ __nv_bfloat16 g_qkv_h[SEQ * NE3];   // qkv split
__device__ __nv_bfloat16 g_qkv_l[SEQ * NE3];
__device__ __nv_bfloat16 g_att_h[SEQ * EMB];   // attention out split
__device__ __nv_bfloat16 g_att_l[SEQ * EMB];

// ---------------------------------------------------------------------------
// helpers
// ---------------------------------------------------------------------------
__device__ __forceinline__ void mma_bf16(float4& d,
    uint32_t a0, uint32_t a1, uint32_t a2, uint32_t a3,
    uint32_t b0, uint32_t b1)
{
    asm volatile(
        "mma.sync.aligned.m16n8k16.row.col.f32.bf16.bf16.f32 "
        "{%0,%1,%2,%3},{%4,%5,%6,%7},{%8,%9},{%0,%1,%2,%3};\n"
        : "+f"(d.x), "+f"(d.y), "+f"(d.z), "+f"(d.w)
        : "r"(a0), "r"(a1), "r"(a2), "r"(a3), "r"(b0), "r"(b1));
}

// split (x,y) into packed bf16x2 hi and lo words; x in low half (even col)
__device__ __forceinline__ void split2b(float x, float y, uint32_t& hi, uint32_t& lo) {
    uint32_t h;
    asm("cvt.rn.bf16x2.f32 %0, %1, %2;" : "=r"(h) : "f"(y), "f"(x));
    float hx = __uint_as_float(h << 16);
    float hy = __uint_as_float(h & 0xffff0000u);
    uint32_t l;
    asm("cvt.rn.bf16x2.f32 %0, %1, %2;" : "=r"(l) : "f"(y - hy), "f"(x - hx));
    hi = h; lo = l;
}

__device__ __forceinline__ void cp16(uint32_t smem_byte_addr, const void* gptr) {
    asm volatile("cp.async.cg.shared.global [%0], [%1], 16;\n"
                 :: "r"(smem_byte_addr), "l"(gptr));
}
__device__ __forceinline__ void cp_commit() {
    asm volatile("cp.async.commit_group;\n");
}
template<int N>
__device__ __forceinline__ void cp_wait() {
    asm volatile("cp.async.wait_group %0;\n" :: "n"(N));
}

// ---------------------------------------------------------------------------
// prep: elementwise split f32 -> bf16 hi/lo (n/4 float4 per thread grid)
// ---------------------------------------------------------------------------
__global__ __launch_bounds__(256) void split_kernel(
    const float4* __restrict__ src, uint2* __restrict__ hi,
    uint2* __restrict__ lo, int n4)
{
    const int i = blockIdx.x * 256 + threadIdx.x;
    if (i >= n4) return;
    float4 v = src[i];
    uint32_t h0, l0, h1, l1;
    split2b(v.x, v.y, h0, l0);
    split2b(v.z, v.w, h1, l1);
    hi[i] = make_uint2(h0, h1);
    lo[i] = make_uint2(l0, l1);
}

// ---------------------------------------------------------------------------
// prep: transpose + split. W [K][N] f32 -> Wt hi/lo [N][K] bf16.
// 32x32 tiles, 256 threads.
// ---------------------------------------------------------------------------
__global__ __launch_bounds__(256) void transpose_split_kernel(
    const float* __restrict__ W, __nv_bfloat16* __restrict__ Th,
    __nv_bfloat16* __restrict__ Tl, int K, int N)
{
    __shared__ float sm[32][33];
    const int n0 = blockIdx.x * 32;
    const int k0 = blockIdx.y * 32;
    const int tid = threadIdx.x;
    #pragma unroll
    for (int it = 0; it < 4; it++) {
        const int f = tid + it * 256;
        const int r = f >> 5, c = f & 31;
        sm[r][c] = W[(size_t)(k0 + r) * N + n0 + c];
    }
    __syncthreads();
    uint32_t* th = (uint32_t*)Th;
    uint32_t* tl = (uint32_t*)Tl;
    #pragma unroll
    for (int it = 0; it < 2; it++) {
        const int f = tid + it * 256;
        const int n = f >> 4, w = f & 15;
        uint32_t h, l;
        split2b(sm[2 * w][n], sm[2 * w + 1][n], h, l);
        const size_t o = (size_t)(n0 + n) * (K >> 1) + (k0 >> 1) + w;
        th[o] = h;
        tl[o] = l;
    }
}

// ---------------------------------------------------------------------------
// bf16x3 GEMM, pre-split inputs: C[M,N] = A[M,K] @ Bt[N,K]^T + bias
// 128x128x32 tiles, 256 threads (8 warps 2x4, warp tile 64x32),
// cp.async 2-stage pipeline. A,Bt are bf16 hi/lo, k-contiguous.
// ---------------------------------------------------------------------------
#define GST 20                     // smem row stride in words (16 data + 4 pad)
#define GEMM_STAGE_WORDS (4 * 128 * GST)   // AsH AsL BsH BsL
#define GEMM_SMEM (2 * GEMM_STAGE_WORDS * 4)

template<bool SPLIT_OUT>
__global__ __launch_bounds__(256) void gemm_pre_kernel(
    const __nv_bfloat16* __restrict__ Ah, const __nv_bfloat16* __restrict__ Al,
    const __nv_bfloat16* __restrict__ Bth, const __nv_bfloat16* __restrict__ Btl,
    const float* __restrict__ bias, float* __restrict__ Cf,
    __nv_bfloat16* __restrict__ Chi, __nv_bfloat16* __restrict__ Clo,
    int M, int N, int K)
{
    extern __shared__ uint32_t sm[];
    const uint32_t smb = (uint32_t)__cvta_generic_to_shared(sm);

    const int tid  = threadIdx.x;
    const int w    = tid >> 5;
    const int lane = tid & 31;
    const int g    = lane >> 2;
    const int tg   = lane & 3;
    const int wm   = (w >> 2) * 64;
    const int wn   = (w & 3) * 32;
    const int m_blk = blockIdx.y * 128;
    const int n_blk = blockIdx.x * 128;

    // per-thread load coords: 2 iterations cover 128 rows x 4 uint4
    const int lrow0 = tid >> 2;           // 0..63
    const int lu4   = tid & 3;            // uint4 col
    const int lcol  = lu4 * 8;            // bf16 col

    float4 acc[4][4];
    #pragma unroll
    for (int i = 0; i < 4; i++)
        #pragma unroll
        for (int j = 0; j < 4; j++) acc[i][j] = make_float4(0.f, 0.f, 0.f, 0.f);

    const int niter = K / 32;

    auto load_stage = [&](int s, int k0) {
        const uint32_t base = smb + s * GEMM_STAGE_WORDS * 4;
        #pragma unroll
        for (int it = 0; it < 2; it++) {
            const int row = lrow0 + it * 64;
            const uint32_t dst = base + (row * GST + lu4 * 4) * 4;
            const size_t ga = (size_t)(m_blk + row) * K + k0 + lcol;
            const size_t gb = (size_t)(n_blk + row) * K + k0 + lcol;
            cp16(dst,                       Ah + ga);
            cp16(dst + 128 * GST * 4,       Al + ga);
            cp16(dst + 2 * 128 * GST * 4,   Bth + gb);
            cp16(dst + 3 * 128 * GST * 4,   Btl + gb);
        }
    };

    load_stage(0, 0);
    cp_commit();

    for (int i = 0; i < niter; i++) {
        if (i + 1 < niter) {
            load_stage((i + 1) & 1, (i + 1) * 32);
            cp_commit();
            cp_wait<1>();
        } else {
            cp_wait<0>();
        }
        __syncthreads();

        const uint32_t* AsH = sm + (i & 1) * GEMM_STAGE_WORDS;
        const uint32_t* AsL = AsH + 128 * GST;
        const uint32_t* BsH = AsL + 128 * GST;
        const uint32_t* BsL = BsH + 128 * GST;

        #pragma unroll
        for (int ks = 0; ks < 2; ks++) {
            const int cp = ks * 8 + tg;
            uint32_t ah[4][4], al[4][4];
            #pragma unroll
            for (int mf = 0; mf < 4; mf++) {
                const int r0 = (wm + mf * 16 + g) * GST;
                const int r1 = r0 + 8 * GST;
                ah[mf][0] = AsH[r0 + cp];     al[mf][0] = AsL[r0 + cp];
                ah[mf][1] = AsH[r1 + cp];     al[mf][1] = AsL[r1 + cp];
                ah[mf][2] = AsH[r0 + cp + 4]; al[mf][2] = AsL[r0 + cp + 4];
                ah[mf][3] = AsH[r1 + cp + 4]; al[mf][3] = AsL[r1 + cp + 4];
            }
            #pragma unroll
            for (int nf = 0; nf < 4; nf++) {
                const int nr = (wn + nf * 8 + g) * GST;
                const uint32_t b0h = BsH[nr + cp];
                const uint32_t b1h = BsH[nr + cp + 4];
                const uint32_t b0l = BsL[nr + cp];
                const uint32_t b1l = BsL[nr + cp + 4];
                #pragma unroll
                for (int mf = 0; mf < 4; mf++) {
                    mma_bf16(acc[mf][nf], ah[mf][0], ah[mf][1], ah[mf][2], ah[mf][3], b0l, b1l);
                    mma_bf16(acc[mf][nf], al[mf][0], al[mf][1], al[mf][2], al[mf][3], b0h, b1h);
                    mma_bf16(acc[mf][nf], ah[mf][0], ah[mf][1], ah[mf][2], ah[mf][3], b0h, b1h);
                }
            }
        }
        __syncthreads();
    }

    // ---- epilogue: bias add, store ----
    #pragma unroll
    for (int nf = 0; nf < 4; nf++) {
        const int c  = n_blk + wn + nf * 8 + 2 * tg;
        const float bc0 = bias[c];
        const float bc1 = bias[c + 1];
        #pragma unroll
        for (int mf = 0; mf < 4; mf++) {
            const int r0 = m_blk + wm + mf * 16 + g;
            const int r1 = r0 + 8;
            float v00 = acc[mf][nf].x + bc0;
            float v01 = acc[mf][nf].y + bc1;
            float v10 = acc[mf][nf].z + bc0;
            float v11 = acc[mf][nf].w + bc1;
            if (SPLIT_OUT) {
                uint32_t h, l;
                split2b(v00, v01, h, l);
                ((uint32_t*)Chi)[((size_t)r0 * N + c) >> 1] = h;
                ((uint32_t*)Clo)[((size_t)r0 * N + c) >> 1] = l;
                split2b(v10, v11, h, l);
                ((uint32_t*)Chi)[((size_t)r1 * N + c) >> 1] = h;
                ((uint32_t*)Clo)[((size_t)r1 * N + c) >> 1] = l;
            } else {
                *(float2*)(Cf + (size_t)r0 * N + c) = make_float2(v00, v01);
                *(float2*)(Cf + (size_t)r1 * N + c) = make_float2(v10, v11);
            }
        }
    }
}

// ---------------------------------------------------------------------------
// Flash attention, causal, NO 1/sqrt(D) scale. bf16x3 m16n8k16 tensor cores.
// Grid (32 q-tiles, 16 heads), 256 threads (8 warps), q-tile 128, k-tile 64.
// Unchanged from R3 except: output written pre-split (bf16 hi/lo).
// ---------------------------------------------------------------------------
#define KPAD 36
#define ATT_SMEM ((64*KPAD*2 + 64*KPAD*2 + 128*KPAD*2) * 4)

__global__ __launch_bounds__(256) void flash_attn_bf16_kernel(
    const __nv_bfloat16* __restrict__ qhi,
    const __nv_bfloat16* __restrict__ qlo,
    __nv_bfloat16* __restrict__ oh,
    __nv_bfloat16* __restrict__ ol)
{
    extern __shared__ uint32_t sm[];
    uint32_t* Ksh = sm;
    uint32_t* Ksl = Ksh + 64 * KPAD;
    uint32_t* Vsh = Ksl + 64 * KPAD;
    uint32_t* Vsl = Vsh + 64 * KPAD;
    uint32_t* Psh = Vsl + 64 * KPAD;
    uint32_t* Psl = Psh + 128 * KPAD;

    const int h   = blockIdx.y;
    const int qt  = gridDim.x - 1 - blockIdx.x;
    const int tid = threadIdx.x;
    const int w    = tid >> 5;
    const int lane = tid & 31;
    const int g    = lane >> 2;
    const int tg   = lane & 3;
    const int m0   = w * 16;
    const int qbase = qt * 128;

    const uint4* qh4 = (const uint4*)qhi;   // row pitch NE3/8 = 384 uint4
    const uint4* ql4 = (const uint4*)qlo;

    #pragma unroll
    for (int i = 0; i < 4; i++) {
        const int f   = tid + i * 256;
        const int row = f >> 3;
        const int c   = f & 7;
        const size_t gidx = (size_t)(qbase + row) * 384 + h * 8 + c;
        *(uint4*)&Psh[row * KPAD + c * 4] = qh4[gidx];
        *(uint4*)&Psl[row * KPAD + c * 4] = ql4[gidx];
    }
    __syncthreads();

    uint32_t qah[4][4], qal[4][4];
    #pragma unroll
    for (int ks = 0; ks < 4; ks++) {
        const int cp = ks * 8 + tg;
        qah[ks][0] = Psh[(m0 + g) * KPAD + cp];
        qah[ks][1] = Psh[(m0 + g + 8) * KPAD + cp];
        qah[ks][2] = Psh[(m0 + g) * KPAD + cp + 4];
        qah[ks][3] = Psh[(m0 + g + 8) * KPAD + cp + 4];
        qal[ks][0] = Psl[(m0 + g) * KPAD + cp];
        qal[ks][1] = Psl[(m0 + g + 8) * KPAD + cp];
        qal[ks][2] = Psl[(m0 + g) * KPAD + cp + 4];
        qal[ks][3] = Psl[(m0 + g + 8) * KPAD + cp + 4];
    }

    float4 of[8];
    #pragma unroll
    for (int nf = 0; nf < 8; nf++) of[nf] = make_float4(0.f, 0.f, 0.f, 0.f);
    float mr0 = -INFINITY, mr1 = -INFINITY, lr0 = 0.f, lr1 = 0.f;

    const int nkt = 2 * (qt + 1);
    for (int kt = 0; kt < nkt; kt++) {
        __syncthreads();

        const int kb = kt * 64;
        #pragma unroll
        for (int i = 0; i < 2; i++) {
            const int f   = tid + i * 256;
            const int key = f >> 3;
            const int c   = f & 7;
            const size_t rb = (size_t)(kb + key) * 384 + h * 8 + c;
            *(uint4*)&Ksh[key * KPAD + c * 4] = qh4[rb + 128];
            *(uint4*)&Ksl[key * KPAD + c * 4] = ql4[rb + 128];
            uint4 vh = qh4[rb + 256];
            uint4 vl = ql4[rb + 256];
            unsigned short* vbh = (unsigned short*)Vsh;
            unsigned short* vbl = (unsigned short*)Vsl;
            const uint32_t wh[4] = {vh.x, vh.y, vh.z, vh.w};
            const uint32_t wl[4] = {vl.x, vl.y, vl.z, vl.w};
            #pragma unroll
            for (int j = 0; j < 4; j++) {
                const int fb = c * 8 + 2 * j;
                vbh[(size_t)fb * (KPAD * 2) + key]       = (unsigned short)(wh[j] & 0xffff);
                vbh[(size_t)(fb + 1) * (KPAD * 2) + key] = (unsigned short)(wh[j] >> 16);
                vbl[(size_t)fb * (KPAD * 2) + key]       = (unsigned short)(wl[j] & 0xffff);
                vbl[(size_t)(fb + 1) * (KPAD * 2) + key] = (unsigned short)(wl[j] >> 16);
            }
        }
        __syncthreads();

        float4 cf[8];
        #pragma unroll
        for (int nf = 0; nf < 8; nf++) cf[nf] = make_float4(0.f, 0.f, 0.f, 0.f);
        #pragma unroll
        for (int ks = 0; ks < 4; ks++) {
            const int kk = ks * 8 + tg;
            #pragma unroll
            for (int nf = 0; nf < 8; nf++) {
                const int kr = (nf * 8 + g) * KPAD;
                uint32_t b0h = Ksh[kr + kk], b1h = Ksh[kr + kk + 4];
                uint32_t b0l = Ksl[kr + kk], b1l = Ksl[kr + kk + 4];
                mma_bf16(cf[nf], qah[ks][0], qah[ks][1], qah[ks][2], qah[ks][3], b0l, b1l);
                mma_bf16(cf[nf], qal[ks][0], qal[ks][1], qal[ks][2], qal[ks][3], b0h, b1h);
                mma_bf16(cf[nf], qah[ks][0], qah[ks][1], qah[ks][2], qah[ks][3], b0h, b1h);
            }
        }

        if (kt >= 2 * qt) {
            const int qr0 = qbase + m0 + g;
            const int qr1 = qr0 + 8;
            #pragma unroll
            for (int nf = 0; nf < 8; nf++) {
                const int c0 = kb + nf * 8 + 2 * tg;
                if (c0 > qr0)     cf[nf].x = -INFINITY;
                if (c0 + 1 > qr0) cf[nf].y = -INFINITY;
                if (c0 > qr1)     cf[nf].z = -INFINITY;
                if (c0 + 1 > qr1) cf[nf].w = -INFINITY;
            }
        }

        float mt0 = -INFINITY, mt1 = -INFINITY;
        #pragma unroll
        for (int nf = 0; nf < 8; nf++) {
            mt0 = fmaxf(mt0, fmaxf(cf[nf].x, cf[nf].y));
            mt1 = fmaxf(mt1, fmaxf(cf[nf].z, cf[nf].w));
        }
        mt0 = fmaxf(mt0, __shfl_xor_sync(0xffffffffu, mt0, 1));
        mt0 = fmaxf(mt0, __shfl_xor_sync(0xffffffffu, mt0, 2));
        mt1 = fmaxf(mt1, __shfl_xor_sync(0xffffffffu, mt1, 1));
        mt1 = fmaxf(mt1, __shfl_xor_sync(0xffffffffu, mt1, 2));

        const float mn0 = fmaxf(mr0, mt0);
        const float mn1 = fmaxf(mr1, mt1);
        const float corr0 = __expf(mr0 - mn0);
        const float corr1 = __expf(mr1 - mn1);
        mr0 = mn0; mr1 = mn1;

        float s0 = 0.f, s1 = 0.f;
        #pragma unroll
        for (int nf = 0; nf < 8; nf++) {
            float p00 = __expf(cf[nf].x - mn0);
            float p01 = __expf(cf[nf].y - mn0);
            float p10 = __expf(cf[nf].z - mn1);
            float p11 = __expf(cf[nf].w - mn1);
            s0 += p00 + p01;
            s1 += p10 + p11;
            uint32_t hh, ll;
            split2b(p00, p01, hh, ll);
            Psh[(m0 + g) * KPAD + nf * 4 + tg] = hh;
            Psl[(m0 + g) * KPAD + nf * 4 + tg] = ll;
            split2b(p10, p11, hh, ll);
            Psh[(m0 + g + 8) * KPAD + nf * 4 + tg] = hh;
            Psl[(m0 + g + 8) * KPAD + nf * 4 + tg] = ll;
        }
        s0 += __shfl_xor_sync(0xffffffffu, s0, 1);
        s0 += __shfl_xor_sync(0xffffffffu, s0, 2);
        s1 += __shfl_xor_sync(0xffffffffu, s1, 1);
        s1 += __shfl_xor_sync(0xffffffffu, s1, 2);
        lr0 = lr0 * corr0 + s0;
        lr1 = lr1 * corr1 + s1;

        #pragma unroll
        for (int nf = 0; nf < 8; nf++) {
            of[nf].x *= corr0; of[nf].y *= corr0;
            of[nf].z *= corr1; of[nf].w *= corr1;
        }
        __syncwarp();

        #pragma unroll
        for (int ks = 0; ks < 4; ks++) {
            const int cp = ks * 8 + tg;
            uint32_t a0h = Psh[(m0 + g) * KPAD + cp];
            uint32_t a1h = Psh[(m0 + g + 8) * KPAD + cp];
            uint32_t a2h = Psh[(m0 + g) * KPAD + cp + 4];
            uint32_t a3h = Psh[(m0 + g + 8) * KPAD + cp + 4];
            uint32_t a0l = Psl[(m0 + g) * KPAD + cp];
            uint32_t a1l = Psl[(m0 + g + 8) * KPAD + cp];
            uint32_t a2l = Psl[(m0 + g) * KPAD + cp + 4];
            uint32_t a3l = Psl[(m0 + g + 8) * KPAD + cp + 4];
            #pragma unroll
            for (int nf = 0; nf < 8; nf++) {
                const int vr = (nf * 8 + g) * KPAD;
                uint32_t b0h = Vsh[vr + cp], b1h = Vsh[vr + cp + 4];
                uint32_t b0l = Vsl[vr + cp], b1l = Vsl[vr + cp + 4];
                mma_bf16(of[nf], a0h, a1h, a2h, a3h, b0l, b1l);
                mma_bf16(of[nf], a0l, a1l, a2l, a3l, b0h, b1h);
                mma_bf16(of[nf], a0h, a1h, a2h, a3h, b0h, b1h);
            }
        }
    }

    // ---- finalize: split-write O ----
    const float i0 = 1.f / lr0;
    const float i1 = 1.f / lr1;
    const int r0 = qbase + m0 + g;
    const int r1 = r0 + 8;
    #pragma unroll
    for (int nf = 0; nf < 8; nf++) {
        const int c = h * HD + nf * 8 + 2 * tg;
        uint32_t hh, ll;
        split2b(of[nf].x * i0, of[nf].y * i0, hh, ll);
        ((uint32_t*)oh)[((size_t)r0 * EMB + c) >> 1] = hh;
        ((uint32_t*)ol)[((size_t)r0 * EMB + c) >> 1] = ll;
        split2b(of[nf].z * i1, of[nf].w * i1, hh, ll);
        ((uint32_t*)oh)[((size_t)r1 * EMB + c) >> 1] = hh;
        ((uint32_t*)ol)[((size_t)r1 * EMB + c) >> 1] = ll;
    }
}

// ---------------------------------------------------------------------------
// kernel_launch
// ---------------------------------------------------------------------------
extern "C" void kernel_launch(void* const* d_in, const int* in_sizes, int n_in,
                              void* d_out, int out_size)
{
    const float* x    = (const float*)d_in[0];
    const float* Wqkv = (const float*)d_in[2];
    const float* bqkv = (const float*)d_in[3];
    const float* Wp   = (const float*)d_in[4];
    const float* bp   = (const float*)d_in[5];
    float* out = (float*)d_out;

    __nv_bfloat16 *xh, *xl, *wqh, *wql, *wph, *wpl, *qkvh, *qkvl, *atth, *attl;
    cudaGetSymbolAddress((void**)&xh,   g_x_h);
    cudaGetSymbolAddress((void**)&xl,   g_x_l);
    cudaGetSymbolAddress((void**)&wqh,  g_wqkv_h);
    cudaGetSymbolAddress((void**)&wql,  g_wqkv_l);
    cudaGetSymbolAddress((void**)&wph,  g_wp_h);
    cudaGetSymbolAddress((void**)&wpl,  g_wp_l);
    cudaGetSymbolAddress((void**)&qkvh, g_qkv_h);
    cudaGetSymbolAddress((void**)&qkvl, g_qkv_l);
    cudaGetSymbolAddress((void**)&atth, g_att_h);
    cudaGetSymbolAddress((void**)&attl, g_att_l);

    // 0) prep: split x, transpose+split weights
    split_kernel<<<SEQ * EMB / 4 / 256, 256>>>(
        (const float4*)x, (uint2*)xh, (uint2*)xl, SEQ * EMB / 4);
    {
        dim3 grid(NE3 / 32, EMB / 32);
        transpose_split_kernel<<<grid, 256>>>(Wqkv, wqh, wql, EMB, NE3);
    }
    {
        dim3 grid(EMB / 32, EMB / 32);
        transpose_split_kernel<<<grid, 256>>>(Wp, wph, wpl, EMB, EMB);
    }

    // 1) QKV projection (pipelined bf16x3) -> split qkv
    {
        cudaFuncSetAttribute(gemm_pre_kernel<true>,
                             cudaFuncAttributeMaxDynamicSharedMemorySize, GEMM_SMEM);
        dim3 grid(NE3 / 128, SEQ / 128);
        gemm_pre_kernel<true><<<grid, 256, GEMM_SMEM>>>(
            xh, xl, wqh, wql, bqkv, nullptr, qkvh, qkvl, SEQ, NE3, EMB);
    }
    // 2) causal flash attention -> split att
    {
        cudaFuncSetAttribute(flash_attn_bf16_kernel,
                             cudaFuncAttributeMaxDynamicSharedMemorySize, ATT_SMEM);
        dim3 grid(SEQ / 128, NH);
        flash_attn_bf16_kernel<<<grid, 256, ATT_SMEM>>>(qkvh, qkvl, atth, attl);
    }
    // 3) output projection -> f32 out
    {
        cudaFuncSetAttribute(gemm_pre_kernel<false>,
                             cudaFuncAttributeMaxDynamicSharedMemorySize, GEMM_SMEM);
        dim3 grid(EMB / 128, SEQ / 128);
        gemm_pre_kernel<false><<<grid, 256, GEMM_SMEM>>>(
            atth, attl, wph, wpl, bp, out, nullptr, nullptr, SEQ, EMB, EMB);
    }
}